// round 7
// baseline (speedup 1.0000x reference)
#include <cuda_runtime.h>

#define HH 1536
#define WW 2048
#define QPR (WW / 4)          // float4 quads per row = 512
#define PLANE (HH * WW)
#define V 4                   // output rows per thread

// Load one input row segment (6 taps: c-1 .. c+4) with relu + zero padding.
// Halos come from neighbor lanes via shuffle; warp-edge lanes fall back to LDG.
__device__ __forceinline__ void load_row(const float* __restrict__ in,
                                         int r, int q, int c, int lane,
                                         float* d) {
    if (r < 0 || r >= HH) {
#pragma unroll
        for (int i = 0; i < 6; i++) d[i] = 0.f;
        return;
    }
    float4 v = __ldg((const float4*)in + r * QPR + q);
    d[1] = fmaxf(v.x, 0.f);
    d[2] = fmaxf(v.y, 0.f);
    d[3] = fmaxf(v.z, 0.f);
    d[4] = fmaxf(v.w, 0.f);
    // neighbor lanes hold adjacent quads of the SAME row -> shuffle the relu'd edges
    float lw = __shfl_up_sync(0xffffffffu, d[4], 1);   // lane-1's col c-1
    float rw = __shfl_down_sync(0xffffffffu, d[1], 1); // lane+1's col c+4
    if (lane == 0)  lw = (c > 0)      ? fmaxf(__ldg(in + r * WW + c - 1), 0.f) : 0.f;
    if (lane == 31) rw = (c + 4 < WW) ? fmaxf(__ldg(in + r * WW + c + 4), 0.f) : 0.f;
    d[0] = lw;
    d[5] = rw;
}

__device__ __forceinline__ void compute_row(const float* r0, const float* r1,
                                            const float* r2,
                                            int h, int c, float s,
                                            float* __restrict__ out, int base) {
    // shared across the 4 pixels of this row
    float cs[6], e[6];
#pragma unroll
    for (int j = 0; j < 6; j++) {
        cs[j] = r0[j] + r1[j] + r2[j];   // column sums (for cnt and w-centroid)
        e[j]  = r2[j] - r0[j];           // row2 - row0 (for h-centroid)
    }
    float hf = (float)h;
    float fo[4], wo[4], ho[4];
#pragma unroll
    for (int p = 0; p < 4; p++) {
        float cnt = cs[p] + cs[p + 1] + cs[p + 2];
        float t4 = r1[p + 1];
        // argmax==center with first-occurrence ties: strict > vs earlier taps, >= vs later
        bool mask = (t4 > r0[p]) & (t4 > r0[p + 1]) & (t4 > r0[p + 2]) & (t4 > r1[p])
                  & (t4 >= r1[p + 2]) & (t4 >= r2[p]) & (t4 >= r2[p + 1]) & (t4 >= r2[p + 2]);
        fo[p] = ((cnt > 0.5f) && mask) ? 1.f : 0.f;

        float inv = __fdividef(1.f, fmaxf(cnt, 1e-12f));
        // (h-1)*r0s + h*r1s + (h+1)*r2s == h*cnt + (r2s - r0s)
        float fh = fmaf(hf, cnt, e[p] + e[p + 1] + e[p + 2]) * inv;
        float wc = (float)(c + p);
        // (w-1)*c0s + w*c1s + (w+1)*c2s == w*cnt + (c2s - c0s)
        float fw = fmaf(wc, cnt, cs[p + 2] - cs[p]) * inv;
        wo[p] = fmaf(s, fw, 0.5f);
        ho[p] = fmaf(s, fh, 0.5f);
    }
    float4* out4 = (float4*)out;
    out4[base]                   = make_float4(fo[0], fo[1], fo[2], fo[3]);
    out4[(PLANE / 4) + base]     = make_float4(wo[0], wo[1], wo[2], wo[3]);
    out4[2 * (PLANE / 4) + base] = make_float4(ho[0], ho[1], ho[2], ho[3]);
}

__global__ __launch_bounds__(256)
void count_stencil_v4(const float* __restrict__ in,
                      const int* __restrict__ stride_p,
                      float* __restrict__ out) {
    int q = blockIdx.x * blockDim.x + threadIdx.x;   // quad index within row (0..511)
    int lane = threadIdx.x & 31;
    int h0 = blockIdx.y * V;
    int c = q << 2;
    float s = (float)(*stride_p);

    // ring buffer of 3 input rows, fully unrolled so indices are static
    float a0[6], a1[6], a2[6];
    load_row(in, h0 - 1, q, c, lane, a0);
    load_row(in, h0,     q, c, lane, a1);

    load_row(in, h0 + 1, q, c, lane, a2);
    compute_row(a0, a1, a2, h0,     c, s, out, (h0)     * QPR + q);

    load_row(in, h0 + 2, q, c, lane, a0);
    compute_row(a1, a2, a0, h0 + 1, c, s, out, (h0 + 1) * QPR + q);

    load_row(in, h0 + 3, q, c, lane, a1);
    compute_row(a2, a0, a1, h0 + 2, c, s, out, (h0 + 2) * QPR + q);

    load_row(in, h0 + 4, q, c, lane, a2);
    compute_row(a0, a1, a2, h0 + 3, c, s, out, (h0 + 3) * QPR + q);
}

extern "C" void kernel_launch(void* const* d_in, const int* in_sizes, int n_in,
                              void* d_out, int out_size) {
    const float* in = (const float*)d_in[0];
    const int* stride_p = (const int*)d_in[2];   // inputs: map, loc_kernel_size, stride
    float* out = (float*)d_out;

    dim3 block(256, 1, 1);
    dim3 grid(QPR / 256, HH / V, 1);             // (2, 384)
    count_stencil_v4<<<grid, block>>>(in, stride_p, out);
}

// round 8
// speedup vs baseline: 1.1597x; 1.1597x over previous
#include <cuda_runtime.h>

#define HH 1536
#define WW 2048
#define QPR (WW / 4)          // float4 quads per row = 512
#define PLANE (HH * WW)

// Load one row's 6 taps (c-1 .. c+4), relu'd. Row guaranteed in bounds.
__device__ __forceinline__ void load_row(const float* __restrict__ in,
                                         int r, int q, int c, float* d) {
    float4 v = __ldg((const float4*)in + r * QPR + q);
    d[1] = fmaxf(v.x, 0.f);
    d[2] = fmaxf(v.y, 0.f);
    d[3] = fmaxf(v.z, 0.f);
    d[4] = fmaxf(v.w, 0.f);
    d[0] = (c > 0)      ? fmaxf(__ldg(in + r * WW + c - 1), 0.f) : 0.f;
    d[5] = (c + 4 < WW) ? fmaxf(__ldg(in + r * WW + c + 4), 0.f) : 0.f;
}

__global__ __launch_bounds__(256)
void count_stencil_k(const float* __restrict__ in,
                     const int* __restrict__ stride_p,
                     float* __restrict__ out) {
    int q = blockIdx.x * blockDim.x + threadIdx.x;   // quad index within row
    int h = blockIdx.y;                               // uniform per block
    int c = q << 2;
    float s = (float)(*stride_p);

    float r0[6], r1[6], r2[6];
    // Block-uniform border branch: only blocks h==0 / h==HH-1 take slow paths.
    if (h > 0 && h < HH - 1) {
        load_row(in, h - 1, q, c, r0);
        load_row(in, h,     q, c, r1);
        load_row(in, h + 1, q, c, r2);
    } else if (h == 0) {
#pragma unroll
        for (int i = 0; i < 6; i++) r0[i] = 0.f;
        load_row(in, 0, q, c, r1);
        load_row(in, 1, q, c, r2);
    } else {
        load_row(in, HH - 2, q, c, r0);
        load_row(in, HH - 1, q, c, r1);
#pragma unroll
        for (int i = 0; i < 6; i++) r2[i] = 0.f;
    }

    // Shared across the 4 pixels of this quad.
    float cs[6], e[6];
#pragma unroll
    for (int j = 0; j < 6; j++) {
        cs[j] = r0[j] + r1[j] + r2[j];   // column sums
        e[j]  = r2[j] - r0[j];           // bottom-row minus top-row (h-centroid delta)
    }

    float hf = (float)h;
    float fo[4], wo[4], ho[4];
#pragma unroll
    for (int p = 0; p < 4; p++) {
        float cnt = cs[p] + cs[p + 1] + cs[p + 2];
        float t4  = r1[p + 1];

        // argmax==center, first-occurrence ties: strictly greater than the max of
        // the 4 earlier taps, >= the max of the 4 later taps. (All values >= 0
        // post-relu, finite -> fmax tree is exact.)
        float emax = fmaxf(fmaxf(r0[p], r0[p + 1]), fmaxf(r0[p + 2], r1[p]));
        float lmax = fmaxf(fmaxf(r1[p + 2], r2[p]), fmaxf(r2[p + 1], r2[p + 2]));
        bool mask  = (t4 > emax) & (t4 >= lmax) & (cnt > 0.5f);
        fo[p] = mask ? 1.f : 0.f;

        float inv = __fdividef(1.f, fmaxf(cnt, 1e-12f));
        // (h-1)*r0s + h*r1s + (h+1)*r2s == h*cnt + (r2s - r0s)
        float fh = fmaf(hf, cnt, e[p] + e[p + 1] + e[p + 2]) * inv;
        float wc = (float)(c + p);
        // (w-1)*c0s + w*c1s + (w+1)*c2s == w*cnt + (c2s - c0s)
        float fw = fmaf(wc, cnt, cs[p + 2] - cs[p]) * inv;
        wo[p] = fmaf(s, fw, 0.5f);
        ho[p] = fmaf(s, fh, 0.5f);
    }

    float4* out4 = (float4*)out;
    int base = h * QPR + q;
    out4[base]                   = make_float4(fo[0], fo[1], fo[2], fo[3]);
    out4[(PLANE / 4) + base]     = make_float4(wo[0], wo[1], wo[2], wo[3]);
    out4[2 * (PLANE / 4) + base] = make_float4(ho[0], ho[1], ho[2], ho[3]);
}

extern "C" void kernel_launch(void* const* d_in, const int* in_sizes, int n_in,
                              void* d_out, int out_size) {
    const float* in = (const float*)d_in[0];
    const int* stride_p = (const int*)d_in[2];   // inputs: map, loc_kernel_size, stride
    float* out = (float*)d_out;

    dim3 block(256, 1, 1);
    dim3 grid(QPR / 256, HH, 1);                 // (2, 1536)
    count_stencil_k<<<grid, block>>>(in, stride_p, out);
}

// round 11
// speedup vs baseline: 1.1800x; 1.0175x over previous
#include <cuda_runtime.h>

#define HH 1536
#define WW 2048
#define QPR (WW / 4)          // float4 quads per row = 512
#define PLANE (HH * WW)
#define FULL 0xffffffffu

__device__ __forceinline__ float relu(float x) { return fmaxf(x, 0.f); }

__global__ __launch_bounds__(256)
void count_stencil_shfl(const float* __restrict__ in,
                        const int* __restrict__ stride_p,
                        float* __restrict__ out) {
    int q = blockIdx.x * blockDim.x + threadIdx.x;   // quad index within row
    int lane = threadIdx.x & 31;
    int h = blockIdx.y;                               // uniform per block
    int c = q << 2;
    float s = (float)(*stride_p);

    const float4* in4 = (const float4*)in;
    float4 v0, v1, v2;
    const float4 z4 = make_float4(0.f, 0.f, 0.f, 0.f);

    // Block-uniform border branch; interior path front-batches 3 independent loads.
    if (h > 0 && h < HH - 1) {
        v0 = __ldg(in4 + (h - 1) * QPR + q);
        v1 = __ldg(in4 + h       * QPR + q);
        v2 = __ldg(in4 + (h + 1) * QPR + q);
    } else if (h == 0) {
        v0 = z4;
        v1 = __ldg(in4 + q);
        v2 = __ldg(in4 + QPR + q);
    } else {
        v0 = __ldg(in4 + (HH - 2) * QPR + q);
        v1 = __ldg(in4 + (HH - 1) * QPR + q);
        v2 = z4;
    }

    float r0[6], r1[6], r2[6];
    r0[1] = relu(v0.x); r0[2] = relu(v0.y); r0[3] = relu(v0.z); r0[4] = relu(v0.w);
    r1[1] = relu(v1.x); r1[2] = relu(v1.y); r1[3] = relu(v1.z); r1[4] = relu(v1.w);
    r2[1] = relu(v2.x); r2[2] = relu(v2.y); r2[3] = relu(v2.z); r2[4] = relu(v2.w);

    // Halos from neighbor lanes (adjacent quads of the same rows).
    r0[0] = __shfl_up_sync(FULL, r0[4], 1);
    r1[0] = __shfl_up_sync(FULL, r1[4], 1);
    r2[0] = __shfl_up_sync(FULL, r2[4], 1);
    r0[5] = __shfl_down_sync(FULL, r0[1], 1);
    r1[5] = __shfl_down_sync(FULL, r1[1], 1);
    r2[5] = __shfl_down_sync(FULL, r2[1], 1);

    // Warp-edge fixups: only lanes 0 and 31 need global halo taps.
    if (lane == 0) {
        bool lv = (c > 0);
        r0[0] = (lv && h > 0)      ? relu(__ldg(in + (h - 1) * WW + c - 1)) : 0.f;
        r1[0] = lv                 ? relu(__ldg(in + h       * WW + c - 1)) : 0.f;
        r2[0] = (lv && h < HH - 1) ? relu(__ldg(in + (h + 1) * WW + c - 1)) : 0.f;
    }
    if (lane == 31) {
        bool rv = (c + 4 < WW);
        r0[5] = (rv && h > 0)      ? relu(__ldg(in + (h - 1) * WW + c + 4)) : 0.f;
        r1[5] = rv                 ? relu(__ldg(in + h       * WW + c + 4)) : 0.f;
        r2[5] = (rv && h < HH - 1) ? relu(__ldg(in + (h + 1) * WW + c + 4)) : 0.f;
    }

    // Shared across the 4 pixels of this quad.
    float cs[6], e[6];
#pragma unroll
    for (int j = 0; j < 6; j++) {
        cs[j] = r0[j] + r1[j] + r2[j];   // column sums
        e[j]  = r2[j] - r0[j];           // bottom-row minus top-row
    }

    float hf = (float)h;
    float fo[4], wo[4], ho[4];
#pragma unroll
    for (int p = 0; p < 4; p++) {
        float cnt = cs[p] + cs[p + 1] + cs[p + 2];
        float t4  = r1[p + 1];

        // argmax==center, first-occurrence ties: strict > vs max of 4 earlier taps,
        // >= vs max of 4 later taps (relu'd values are finite, >= 0 -> exact).
        float emax = fmaxf(fmaxf(r0[p], r0[p + 1]), fmaxf(r0[p + 2], r1[p]));
        float lmax = fmaxf(fmaxf(r1[p + 2], r2[p]), fmaxf(r2[p + 1], r2[p + 2]));
        bool mask  = (t4 > emax) & (t4 >= lmax) & (cnt > 0.5f);
        fo[p] = mask ? 1.f : 0.f;

        float inv = __fdividef(1.f, fmaxf(cnt, 1e-12f));
        // (h-1)*r0s + h*r1s + (h+1)*r2s == h*cnt + (r2s - r0s)
        float fh = fmaf(hf, cnt, e[p] + e[p + 1] + e[p + 2]) * inv;
        float wc = (float)(c + p);
        // (w-1)*c0s + w*c1s + (w+1)*c2s == w*cnt + (c2s - c0s)
        float fw = fmaf(wc, cnt, cs[p + 2] - cs[p]) * inv;
        wo[p] = fmaf(s, fw, 0.5f);
        ho[p] = fmaf(s, fh, 0.5f);
    }

    float4* out4 = (float4*)out;
    int base = h * QPR + q;
    out4[base]                   = make_float4(fo[0], fo[1], fo[2], fo[3]);
    out4[(PLANE / 4) + base]     = make_float4(wo[0], wo[1], wo[2], wo[3]);
    out4[2 * (PLANE / 4) + base] = make_float4(ho[0], ho[1], ho[2], ho[3]);
}

extern "C" void kernel_launch(void* const* d_in, const int* in_sizes, int n_in,
                              void* d_out, int out_size) {
    const float* in = (const float*)d_in[0];
    const int* stride_p = (const int*)d_in[2];   // inputs: map, loc_kernel_size, stride
    float* out = (float*)d_out;

    dim3 block(256, 1, 1);
    dim3 grid(QPR / 256, HH, 1);                 // (2, 1536)
    count_stencil_shfl<<<grid, block>>>(in, stride_p, out);
}

// round 12
// speedup vs baseline: 1.1980x; 1.0152x over previous
#include <cuda_runtime.h>

#define HH 1536
#define WW 2048
#define QPR (WW / 4)          // float4 quads per row = 512
#define PLANE (HH * WW)
#define FULL 0xffffffffu

__device__ __forceinline__ float relu(float x) { return fmaxf(x, 0.f); }

// One output row's 4 pixels. rt/rm/rb = top/mid/bottom tap rows (6 cols each),
// cs = 3-row column sums, e = rb - rt (per column).
__device__ __forceinline__ void compute_row(const float* rt, const float* rm,
                                            const float* rb,
                                            const float* cs, const float* e,
                                            int h, int c, float s,
                                            float* __restrict__ out, int base) {
    float hf = (float)h;
    float fo[4], wo[4], ho[4];
#pragma unroll
    for (int p = 0; p < 4; p++) {
        float cnt = cs[p] + cs[p + 1] + cs[p + 2];
        float t4  = rm[p + 1];
        // argmax==center, first-occurrence ties: strict > vs max of the 4 earlier
        // taps, >= vs max of the 4 later taps (relu'd values finite, >= 0).
        float emax = fmaxf(fmaxf(rt[p], rt[p + 1]), fmaxf(rt[p + 2], rm[p]));
        float lmax = fmaxf(fmaxf(rm[p + 2], rb[p]), fmaxf(rb[p + 1], rb[p + 2]));
        bool mask  = (t4 > emax) & (t4 >= lmax) & (cnt > 0.5f);
        fo[p] = mask ? 1.f : 0.f;

        float inv = __fdividef(1.f, fmaxf(cnt, 1e-12f));
        // (h-1)*rts + h*rms + (h+1)*rbs == h*cnt + (rbs - rts)
        float fh = fmaf(hf, cnt, e[p] + e[p + 1] + e[p + 2]) * inv;
        float wc = (float)(c + p);
        // (w-1)*c0s + w*c1s + (w+1)*c2s == w*cnt + (c2s - c0s)
        float fw = fmaf(wc, cnt, cs[p + 2] - cs[p]) * inv;
        wo[p] = fmaf(s, fw, 0.5f);
        ho[p] = fmaf(s, fh, 0.5f);
    }
    float4* out4 = (float4*)out;
    out4[base]                   = make_float4(fo[0], fo[1], fo[2], fo[3]);
    out4[(PLANE / 4) + base]     = make_float4(wo[0], wo[1], wo[2], wo[3]);
    out4[2 * (PLANE / 4) + base] = make_float4(ho[0], ho[1], ho[2], ho[3]);
}

__global__ __launch_bounds__(256)
void count_stencil_v2(const float* __restrict__ in,
                      const int* __restrict__ stride_p,
                      float* __restrict__ out) {
    int q = blockIdx.x * blockDim.x + threadIdx.x;   // quad index within row
    int lane = threadIdx.x & 31;
    int by = blockIdx.y;
    int h0 = by << 1;                                 // first of 2 output rows
    int c = q << 2;
    float s = (float)(*stride_p);

    const float4* in4 = (const float4*)in;
    float4 v0, v1, v2, v3;
    const float4 z4 = make_float4(0.f, 0.f, 0.f, 0.f);

    // Block-uniform border branch; interior path front-batches 4 independent loads.
    if (by > 0 && by < (HH / 2 - 1)) {
        v0 = __ldg(in4 + (h0 - 1) * QPR + q);
        v1 = __ldg(in4 + (h0    ) * QPR + q);
        v2 = __ldg(in4 + (h0 + 1) * QPR + q);
        v3 = __ldg(in4 + (h0 + 2) * QPR + q);
    } else if (by == 0) {
        v0 = z4;
        v1 = __ldg(in4 + q);
        v2 = __ldg(in4 + QPR + q);
        v3 = __ldg(in4 + 2 * QPR + q);
    } else {
        v0 = __ldg(in4 + (HH - 3) * QPR + q);
        v1 = __ldg(in4 + (HH - 2) * QPR + q);
        v2 = __ldg(in4 + (HH - 1) * QPR + q);
        v3 = z4;
    }

    float r0[6], r1[6], r2[6], r3[6];
    r0[1] = relu(v0.x); r0[2] = relu(v0.y); r0[3] = relu(v0.z); r0[4] = relu(v0.w);
    r1[1] = relu(v1.x); r1[2] = relu(v1.y); r1[3] = relu(v1.z); r1[4] = relu(v1.w);
    r2[1] = relu(v2.x); r2[2] = relu(v2.y); r2[3] = relu(v2.z); r2[4] = relu(v2.w);
    r3[1] = relu(v3.x); r3[2] = relu(v3.y); r3[3] = relu(v3.z); r3[4] = relu(v3.w);

    // Halos from neighbor lanes (adjacent quads of the same rows).
    r0[0] = __shfl_up_sync(FULL, r0[4], 1);
    r1[0] = __shfl_up_sync(FULL, r1[4], 1);
    r2[0] = __shfl_up_sync(FULL, r2[4], 1);
    r3[0] = __shfl_up_sync(FULL, r3[4], 1);
    r0[5] = __shfl_down_sync(FULL, r0[1], 1);
    r1[5] = __shfl_down_sync(FULL, r1[1], 1);
    r2[5] = __shfl_down_sync(FULL, r2[1], 1);
    r3[5] = __shfl_down_sync(FULL, r3[1], 1);

    // Warp-edge fixups: only lanes 0 and 31 need global halo taps.
    // (h0 >= 0, h0+1 <= HH-1 always; h0-1 / h0+2 validity is border-dependent.)
    if (lane == 0) {
        bool lv = (c > 0);
        r0[0] = (lv && h0 > 0)       ? relu(__ldg(in + (h0 - 1) * WW + c - 1)) : 0.f;
        r1[0] = lv                   ? relu(__ldg(in + (h0    ) * WW + c - 1)) : 0.f;
        r2[0] = lv                   ? relu(__ldg(in + (h0 + 1) * WW + c - 1)) : 0.f;
        r3[0] = (lv && h0 + 2 < HH)  ? relu(__ldg(in + (h0 + 2) * WW + c - 1)) : 0.f;
    }
    if (lane == 31) {
        bool rv = (c + 4 < WW);
        r0[5] = (rv && h0 > 0)       ? relu(__ldg(in + (h0 - 1) * WW + c + 4)) : 0.f;
        r1[5] = rv                   ? relu(__ldg(in + (h0    ) * WW + c + 4)) : 0.f;
        r2[5] = rv                   ? relu(__ldg(in + (h0 + 1) * WW + c + 4)) : 0.f;
        r3[5] = (rv && h0 + 2 < HH)  ? relu(__ldg(in + (h0 + 2) * WW + c + 4)) : 0.f;
    }

    // Column sums for both output rows; the middle pair-sum is shared.
    float csA[6], csB[6], eA[6], eB[6];
#pragma unroll
    for (int j = 0; j < 6; j++) {
        float m = r1[j] + r2[j];
        csA[j] = r0[j] + m;      // rows h0-1 .. h0+1
        csB[j] = m + r3[j];      // rows h0   .. h0+2
        eA[j]  = r2[j] - r0[j];
        eB[j]  = r3[j] - r1[j];
    }

    compute_row(r0, r1, r2, csA, eA, h0,     c, s, out, (h0)     * QPR + q);
    compute_row(r1, r2, r3, csB, eB, h0 + 1, c, s, out, (h0 + 1) * QPR + q);
}

extern "C" void kernel_launch(void* const* d_in, const int* in_sizes, int n_in,
                              void* d_out, int out_size) {
    const float* in = (const float*)d_in[0];
    const int* stride_p = (const int*)d_in[2];   // inputs: map, loc_kernel_size, stride
    float* out = (float*)d_out;

    dim3 block(256, 1, 1);
    dim3 grid(QPR / 256, HH / 2, 1);             // (2, 768)
    count_stencil_v2<<<grid, block>>>(in, stride_p, out);
}